// round 1
// baseline (speedup 1.0000x reference)
#include <cuda_runtime.h>
#include <cstdint>

// Problem constants (fixed by the reference):
//   COMPLEXES=2048, RESY=RESX=16, FEAT=64, P=RATE*RATE=256
// map: [C, 16, 16, 64] f32 ; u,v: [C, 256] f32 ; out: [C, 256, 64] f32

constexpr int C_    = 2048;
constexpr int H_    = 16;
constexpr int W_    = 16;
constexpr int F_    = 64;
constexpr int P_    = 256;
constexpr int TILE_FLOATS = H_ * W_ * F_;          // 16384 floats = 64 KB
constexpr int THREADS     = 256;

// Dynamic smem layout:
//   [0, 65536)            : map tile (float, 16B-aligned)
//   [65536, 65536+1024)   : s_off  (int,   per-sample cell offset in floats)
//   [.. +1024)            : s_fx
//   [.. +1024)            : s_fy
constexpr int SMEM_TILE_BYTES = TILE_FLOATS * 4;   // 65536
constexpr int SMEM_TOTAL      = SMEM_TILE_BYTES + 3 * P_ * 4;  // 68608

__global__ __launch_bounds__(THREADS, 3)
void ngf_texture_fetch_kernel(const float* __restrict__ gmap,
                              const float* __restrict__ gu,
                              const float* __restrict__ gv,
                              float* __restrict__ gout)
{
    extern __shared__ __align__(16) float smem[];
    float* tile = smem;                                   // 16384 floats
    int*   s_off = (int*)(smem + TILE_FLOATS);            // 256 ints
    float* s_fx  = (float*)(s_off + P_);                  // 256 floats
    float* s_fy  = s_fx + P_;                             // 256 floats

    const int c = blockIdx.x;
    const int t = threadIdx.x;

    // ---- Stage 1: stream the 64KB map tile into shared (coalesced float4) ----
    {
        const float4* src = (const float4*)(gmap + (size_t)c * TILE_FLOATS);
        float4* dst = (float4*)tile;
        #pragma unroll
        for (int i = 0; i < (TILE_FLOATS / 4) / THREADS; ++i) {   // 16 iters
            dst[i * THREADS + t] = src[i * THREADS + t];
        }
    }

    // ---- Stage 2: per-sample params (1 sample per thread, P_ == THREADS) ----
    {
        const float uu = gu[(size_t)c * P_ + t];
        const float vv = gv[(size_t)c * P_ + t];
        const float x = uu * (float)(W_ - 1);
        const float y = vv * (float)(H_ - 1);
        int x0 = (int)floorf(x);
        int y0 = (int)floorf(y);
        x0 = min(max(x0, 0), W_ - 2);
        y0 = min(max(y0, 0), H_ - 2);
        s_fx[t]  = x - (float)x0;
        s_fy[t]  = y - (float)y0;
        s_off[t] = (y0 * W_ + x0) * F_;
    }

    __syncthreads();

    // ---- Stage 3: bilinear gather + fully coalesced float4 stores ----
    // Thread t: sample sl = t>>4 within each group of 16, feature quad fq = t&15.
    float4* out4 = (float4*)(gout + (size_t)c * P_ * F_);
    const int fq = (t & 15);
    const int sl = (t >> 4);

    #pragma unroll
    for (int it = 0; it < P_ / 16; ++it) {                 // 16 iterations
        const int s   = it * 16 + sl;
        const int off = s_off[s] + fq * 4;                 // broadcast within 16 lanes
        const float fx = s_fx[s];
        const float fy = s_fy[s];

        const float4 g00 = *(const float4*)(tile + off);
        const float4 g01 = *(const float4*)(tile + off + F_);
        const float4 g10 = *(const float4*)(tile + off + W_ * F_);
        const float4 g11 = *(const float4*)(tile + off + W_ * F_ + F_);

        const float w11 = fx * fy;
        const float w01 = fx - w11;          // fx*(1-fy)
        const float w10 = fy - w11;          // (1-fx)*fy
        const float w00 = 1.0f - fx - fy + w11;

        float4 r;
        r.x = g00.x * w00 + g01.x * w01 + g10.x * w10 + g11.x * w11;
        r.y = g00.y * w00 + g01.y * w01 + g10.y * w10 + g11.y * w11;
        r.z = g00.z * w00 + g01.z * w01 + g10.z * w10 + g11.z * w11;
        r.w = g00.w * w00 + g01.w * w01 + g10.w * w10 + g11.w * w11;

        out4[s * (F_ / 4) + fq] = r;
    }
}

extern "C" void kernel_launch(void* const* d_in, const int* in_sizes, int n_in,
                              void* d_out, int out_size)
{
    const float* gmap = (const float*)d_in[0];
    const float* gu   = (const float*)d_in[1];
    const float* gv   = (const float*)d_in[2];
    float* gout       = (float*)d_out;

    // 68.6 KB dynamic smem > 48 KB default: opt in (idempotent host call,
    // not a stream op, graph-capture safe).
    cudaFuncSetAttribute(ngf_texture_fetch_kernel,
                         cudaFuncAttributeMaxDynamicSharedMemorySize, SMEM_TOTAL);

    ngf_texture_fetch_kernel<<<C_, THREADS, SMEM_TOTAL>>>(gmap, gu, gv, gout);
}